// round 11
// baseline (speedup 1.0000x reference)
#include <cuda_runtime.h>
#include <cuda_fp16.h>
#include <stdint.h>

// MultiLevelSparseHashEncoding — round 10.
// vs R9 (101.5us: xT 6.7 + main ~74 + outT ~20):
//  * main: gather keys pre-scaled to BYTE offsets (kx4/kyz4/mask4) so a
//    hashed corner id is ONE LOP3 ((kx4^kyz4)&mask4) + IADD + LDS + HFMA2
//    (-2 instr/corner, ~-30 instr per point-pair).
//  * x-transpose: 8 pts/thread (6 independent LDG.128, latency-bound fix).
//  * rest identical to R9 (rel_err 5.23e-4 validated).

#define NLVL 16
#define NENC 16384
#define NPTS (1 << 20)
#define TPB  1024
#define NPAIR 8
#define NSLICE 18
#define SLICE ((NPTS + NSLICE - 1) / NSLICE)       // 58255
#define SMEM_BYTES ((2 * (NENC + 1)) * (int)sizeof(__half2))   // 131080
#define SCALE    4096.0f
#define INV_SCALE (1.0f / 4096.0f)

__constant__ int c_res[NLVL] = {16, 20, 25, 32, 40, 50, 64, 80,
                                101, 128, 161, 203, 256, 322, 406, 512};
__constant__ int c_nle[NLVL] = {4096, 8000, 15625, 16384, 16384, 16384,
                                16384, 16384, 16384, 16384, 16384, 16384,
                                16384, 16384, 16384, 16384};

__device__ float g_xs[3u * NPTS];                  // SoA coords (12 MB)
__device__ uint2 g_stage[(size_t)NPAIR * NPTS];    // [pair][point] half4 bits

// ---------------------------------------------------------------- pre-kernel
// 8 points per thread: 6 independent LDG.128 -> 6 STG.128 (latency-bound fix)
__global__ __launch_bounds__(512)
void transpose_x_kernel(const float4* __restrict__ x4)
{
    const int i0 = (blockIdx.x * 512 + threadIdx.x) * 2;   // float4-group idx
    float4* __restrict__ p0 = reinterpret_cast<float4*>(g_xs);
    float4* __restrict__ p1 = reinterpret_cast<float4*>(g_xs + NPTS);
    float4* __restrict__ p2 = reinterpret_cast<float4*>(g_xs + 2u * NPTS);

    const float4 a0 = x4[3 * i0 + 0];
    const float4 b0 = x4[3 * i0 + 1];
    const float4 c0 = x4[3 * i0 + 2];
    const float4 a1 = x4[3 * i0 + 3];
    const float4 b1 = x4[3 * i0 + 4];
    const float4 c1 = x4[3 * i0 + 5];

    p0[i0]     = make_float4(a0.x, a0.w, b0.z, c0.y);
    p1[i0]     = make_float4(a0.y, b0.x, b0.w, c0.z);
    p2[i0]     = make_float4(a0.z, b0.y, c0.x, c0.w);
    p0[i0 + 1] = make_float4(a1.x, a1.w, b1.z, c1.y);
    p1[i0 + 1] = make_float4(a1.y, b1.x, b1.w, c1.z);
    p2[i0 + 1] = make_float4(a1.z, b1.y, c1.x, c1.w);
}

// ---------------------------------------------------------------- per-level
// returns the fp16 accumulator still scaled by 2^12
template <bool DIRECT>
__device__ __forceinline__ __half2
level_feat(const char* __restrict__ tabc, const int R,
           const float xv0, const float xv1, const float xv2)
{
    const float halfR = 0.5f * (float)R;
    const float cadd  = halfR - 0.5f;
    const float t0 = fmaf(xv0, halfR, cadd);
    const float t1 = fmaf(xv1, halfR, cadd);
    const float t2 = fmaf(xv2, halfR, cadd);

    const float fl0 = floorf(t0), fl1 = floorf(t1), fl2 = floorf(t2);
    const float fr0 = t0 - fl0, fr1 = t1 - fl1, fr2 = t2 - fl2;
    const int   i0  = (int)fl0, i1 = (int)fl1, i2 = (int)fl2;

    // validity folded into per-dim weights: invalid corner -> weight 0
    const float wx0 = i0     >= 0 ? 1.0f - fr0 : 0.0f;
    const float wx1 = i0 + 1 <  R ? fr0        : 0.0f;
    const float wy0 = i1     >= 0 ? 1.0f - fr1 : 0.0f;
    const float wy1 = i1 + 1 <  R ? fr1        : 0.0f;
    const float wz[2] = {i2     >= 0 ? 1.0f - fr2 : 0.0f,
                         i2 + 1 <  R ? fr2        : 0.0f};
    const float wxy[4] = {wx0 * wy0, wx0 * wy1, wx1 * wy0, wx1 * wy1};

    // keys pre-scaled to BYTE offsets (<<2): hashed id = one LOP3
    unsigned kx4[2], kyz4[4];
    if (DIRECT) {
        const int R2 = R * R;
        const int a0 = max(i0, 0), a1 = min(i0 + 1, R - 1);
        const int b0 = max(i1, 0), b1 = min(i1 + 1, R - 1);
        const int d0 = max(i2, 0), d1 = min(i2 + 1, R - 1);
        kx4[0] = (unsigned)(a0 * R2) << 2; kx4[1] = (unsigned)(a1 * R2) << 2;
        kyz4[0] = (unsigned)(b0 * R + d0) << 2;
        kyz4[1] = (unsigned)(b0 * R + d1) << 2;
        kyz4[2] = (unsigned)(b1 * R + d0) << 2;
        kyz4[3] = (unsigned)(b1 * R + d1) << 2;
    } else {
        kx4[0] = (unsigned)i0 << 2; kx4[1] = (unsigned)(i0 + 1) << 2;
        const unsigned hy0 = (unsigned)i1 * 2654435761u;
        const unsigned hy1 = hy0 + 2654435761u;
        const unsigned hz0 = (unsigned)i2 * 805459861u;
        const unsigned hz1 = hz0 + 805459861u;
        kyz4[0] = (hy0 ^ hz0) << 2; kyz4[1] = (hy0 ^ hz1) << 2;
        kyz4[2] = (hy1 ^ hz0) << 2; kyz4[3] = (hy1 ^ hz1) << 2;
    }
    const unsigned mask4 = (NENC - 1) << 2;

    __half2 acc = __float2half2_rn(0.0f);
    #pragma unroll
    for (int c = 0; c < 8; ++c) {
        const int ox = (c >> 2) & 1, oyz = c & 3;
        unsigned off;
        if (DIRECT) off = kx4[ox] + kyz4[oyz];
        else        off = (kx4[ox] ^ kyz4[oyz]) & mask4;   // single LOP3
        const float   w  = wxy[2 * ox + (oyz >> 1)] * wz[oyz & 1];
        const __half2 w2 = __float2half2_rn(w);
        const __half2 e  = *reinterpret_cast<const __half2*>(tabc + off);
        acc = __hfma2(w2, e, acc);
    }
    return acc;
}

// ---------------------------------------------------------------- main
__global__ __launch_bounds__(TPB, 1)
void hashgrid_pair_kernel(const float* __restrict__ emb)
{
    extern __shared__ __half2 tab[];

    const int m     = blockIdx.x & (NPAIR - 1);   // pair index (fastest)
    const int slice = blockIdx.x >> 3;            // 0..NSLICE-1
    const int lA = 2 * m, lB = 2 * m + 1;
    const int RA = c_res[lA], RB = c_res[lB];
    const int neA = c_nle[lA], neB = c_nle[lB];

    __half2* tabA = tab;
    __half2* tabB = tab + (neA + 1);

    // stage both tables ONCE (persistent over ~58K points)
    const float2* __restrict__ srcA =
        reinterpret_cast<const float2*>(emb) + (size_t)lA * (NENC + 1);
    const float2* __restrict__ srcB =
        reinterpret_cast<const float2*>(emb) + (size_t)lB * (NENC + 1);
    for (int i = threadIdx.x; i <= neA; i += TPB) {
        const float2 v = srcA[i];
        tabA[i] = __floats2half2_rn(v.x * SCALE, v.y * SCALE);
    }
    for (int i = threadIdx.x; i <= neB; i += TPB) {
        const float2 v = srcB[i];
        tabB[i] = __floats2half2_rn(v.x * SCALE, v.y * SCALE);
    }
    __syncthreads();

    const char* tabAc = reinterpret_cast<const char*>(tabA);
    const char* tabBc = reinterpret_cast<const char*>(tabB);
    uint2* __restrict__ stage = g_stage + (size_t)m * NPTS;

    const int pend = min((slice + 1) * SLICE, NPTS);
    #pragma unroll 1
    for (int p = slice * SLICE + threadIdx.x; p < pend; p += TPB) {
        const float xv0 = g_xs[p];
        const float xv1 = g_xs[NPTS + p];
        const float xv2 = g_xs[2u * NPTS + p];

        __half2 rA, rB;
        if (lA < 3) rA = level_feat<true >(tabAc, RA, xv0, xv1, xv2);
        else        rA = level_feat<false>(tabAc, RA, xv0, xv1, xv2);
        if (lB < 3) rB = level_feat<true >(tabBc, RB, xv0, xv1, xv2);
        else        rB = level_feat<false>(tabBc, RB, xv0, xv1, xv2);

        stage[p] = make_uint2(*reinterpret_cast<unsigned*>(&rA),
                              *reinterpret_cast<unsigned*>(&rB));
    }
}

// ---------------------------------------------------------------- transpose
#define TPB3 256
__global__ __launch_bounds__(TPB3)
void transpose_out_kernel(float4* __restrict__ out)
{
    __shared__ uint2 arr[TPB3][NPAIR + 1];        // [point][pair], pitch 9

    const int base = blockIdx.x * TPB3;
    const int tid  = threadIdx.x;

    #pragma unroll
    for (int m = 0; m < NPAIR; ++m)
        arr[tid][m] = g_stage[(size_t)m * NPTS + base + tid];
    __syncthreads();

    #pragma unroll
    for (int k = 0; k < 8; ++k) {
        const int local = k * TPB3 + tid;         // float4 index within block
        const int p_off = local >> 3;
        const int m     = local & 7;
        const uint2 v = arr[p_off][m];
        const float2 fa = __half22float2(*reinterpret_cast<const __half2*>(&v.x));
        const float2 fb = __half22float2(*reinterpret_cast<const __half2*>(&v.y));
        out[(size_t)base * 8 + local] =
            make_float4(fa.x * INV_SCALE, fa.y * INV_SCALE,
                        fb.x * INV_SCALE, fb.y * INV_SCALE);
    }
}

// ---------------------------------------------------------------- launch
extern "C" void kernel_launch(void* const* d_in, const int* in_sizes, int n_in,
                              void* d_out, int out_size)
{
    (void)n_in; (void)out_size;
    const float* x;
    const float* emb;
    if (in_sizes[0] == 3 * NPTS) { x = (const float*)d_in[0]; emb = (const float*)d_in[1]; }
    else                         { x = (const float*)d_in[1]; emb = (const float*)d_in[0]; }
    float4* out = (float4*)d_out;

    cudaFuncSetAttribute(hashgrid_pair_kernel,
                         cudaFuncAttributeMaxDynamicSharedMemorySize, SMEM_BYTES);

    transpose_x_kernel<<<NPTS / 8 / 512, 512>>>(
        reinterpret_cast<const float4*>(x));

    const int blocks = NPAIR * NSLICE;            // 144 = exactly 1 wave
    hashgrid_pair_kernel<<<blocks, TPB, SMEM_BYTES>>>(emb);

    transpose_out_kernel<<<NPTS / TPB3, TPB3>>>(out);
}

// round 13
// speedup vs baseline: 1.0214x; 1.0214x over previous
#include <cuda_runtime.h>
#include <cuda_fp16.h>
#include <stdint.h>

// MultiLevelSparseHashEncoding — round 11.
// R10 regressed (x-T grid too small; byte-offset fold neutral).  Revert to
// the R9 101.5us configuration and add only:
//  * out-transpose writes with __stcs (evict-first) so the 128MB output
//    stream doesn't evict the L2-resident 64MB stage mid-kernel.
//  * out-transpose TPB 256 -> 512 (more ILP, fewer blocks).
// Main kernel and x-transpose byte-identical to R9 (101.5us, 5.23e-4).

#define NLVL 16
#define NENC 16384
#define NPTS (1 << 20)
#define TPB  1024
#define NPAIR 8
#define NSLICE 18
#define SLICE ((NPTS + NSLICE - 1) / NSLICE)       // 58255
#define SMEM_BYTES ((2 * (NENC + 1)) * (int)sizeof(__half2))   // 131080
#define SCALE    4096.0f
#define INV_SCALE (1.0f / 4096.0f)

__constant__ int c_res[NLVL] = {16, 20, 25, 32, 40, 50, 64, 80,
                                101, 128, 161, 203, 256, 322, 406, 512};
__constant__ int c_nle[NLVL] = {4096, 8000, 15625, 16384, 16384, 16384,
                                16384, 16384, 16384, 16384, 16384, 16384,
                                16384, 16384, 16384, 16384};

__device__ float g_xs[3u * NPTS];                  // SoA coords (12 MB)
__device__ uint2 g_stage[(size_t)NPAIR * NPTS];    // [pair][point] half4 bits

// ---------------------------------------------------------------- pre-kernel
// 4 points per thread: 3 float4 loads -> 3 float4 plane stores (R9 form)
__global__ __launch_bounds__(256)
void transpose_x_kernel(const float4* __restrict__ x4)
{
    const int i = blockIdx.x * 256 + threadIdx.x;      // float4-group index
    const float4 a = x4[3 * i + 0];                    // x0 y0 z0 x1
    const float4 b = x4[3 * i + 1];                    // y1 z1 x2 y2
    const float4 c = x4[3 * i + 2];                    // z2 x3 y3 z3
    float4* __restrict__ p0 = reinterpret_cast<float4*>(g_xs);
    float4* __restrict__ p1 = reinterpret_cast<float4*>(g_xs + NPTS);
    float4* __restrict__ p2 = reinterpret_cast<float4*>(g_xs + 2u * NPTS);
    p0[i] = make_float4(a.x, a.w, b.z, c.y);
    p1[i] = make_float4(a.y, b.x, b.w, c.z);
    p2[i] = make_float4(a.z, b.y, c.x, c.w);
}

// ---------------------------------------------------------------- per-level
// returns the fp16 accumulator still scaled by 2^12
template <bool DIRECT>
__device__ __forceinline__ __half2
level_feat(const __half2* __restrict__ tab, const int R,
           const float xv0, const float xv1, const float xv2)
{
    const float halfR = 0.5f * (float)R;
    const float cadd  = halfR - 0.5f;
    const float t0 = fmaf(xv0, halfR, cadd);
    const float t1 = fmaf(xv1, halfR, cadd);
    const float t2 = fmaf(xv2, halfR, cadd);

    const float fl0 = floorf(t0), fl1 = floorf(t1), fl2 = floorf(t2);
    const float fr0 = t0 - fl0, fr1 = t1 - fl1, fr2 = t2 - fl2;
    const int   i0  = (int)fl0, i1 = (int)fl1, i2 = (int)fl2;

    // validity folded into per-dim weights: invalid corner -> weight 0
    const float wx0 = i0     >= 0 ? 1.0f - fr0 : 0.0f;
    const float wx1 = i0 + 1 <  R ? fr0        : 0.0f;
    const float wy0 = i1     >= 0 ? 1.0f - fr1 : 0.0f;
    const float wy1 = i1 + 1 <  R ? fr1        : 0.0f;
    const float wz[2] = {i2     >= 0 ? 1.0f - fr2 : 0.0f,
                         i2 + 1 <  R ? fr2        : 0.0f};
    const float wxy[4] = {wx0 * wy0, wx0 * wy1, wx1 * wy0, wx1 * wy1};

    unsigned kx[2], kyz[4];
    if (DIRECT) {
        const int R2 = R * R;
        const int a0 = max(i0, 0), a1 = min(i0 + 1, R - 1);
        const int b0 = max(i1, 0), b1 = min(i1 + 1, R - 1);
        const int d0 = max(i2, 0), d1 = min(i2 + 1, R - 1);
        kx[0] = (unsigned)(a0 * R2); kx[1] = (unsigned)(a1 * R2);
        kyz[0] = (unsigned)(b0 * R + d0); kyz[1] = (unsigned)(b0 * R + d1);
        kyz[2] = (unsigned)(b1 * R + d0); kyz[3] = (unsigned)(b1 * R + d1);
    } else {
        kx[0] = (unsigned)i0; kx[1] = (unsigned)(i0 + 1);
        const unsigned hy0 = (unsigned)i1 * 2654435761u;
        const unsigned hy1 = hy0 + 2654435761u;
        const unsigned hz0 = (unsigned)i2 * 805459861u;
        const unsigned hz1 = hz0 + 805459861u;
        kyz[0] = hy0 ^ hz0; kyz[1] = hy0 ^ hz1;
        kyz[2] = hy1 ^ hz0; kyz[3] = hy1 ^ hz1;
    }
    const unsigned mask = NENC - 1;

    __half2 acc = __float2half2_rn(0.0f);
    #pragma unroll
    for (int c = 0; c < 8; ++c) {
        const int ox = (c >> 2) & 1, oyz = c & 3;
        unsigned id;
        if (DIRECT) id = kx[ox] + kyz[oyz];
        else        id = (kx[ox] ^ kyz[oyz]) & mask;   // single LOP3
        const float   w  = wxy[2 * ox + (oyz >> 1)] * wz[oyz & 1];
        const __half2 w2 = __float2half2_rn(w);
        acc = __hfma2(w2, tab[id], acc);
    }
    return acc;
}

// ---------------------------------------------------------------- main
__global__ __launch_bounds__(TPB, 1)
void hashgrid_pair_kernel(const float* __restrict__ emb)
{
    extern __shared__ __half2 tab[];

    const int m     = blockIdx.x & (NPAIR - 1);   // pair index (fastest)
    const int slice = blockIdx.x >> 3;            // 0..NSLICE-1
    const int lA = 2 * m, lB = 2 * m + 1;
    const int RA = c_res[lA], RB = c_res[lB];
    const int neA = c_nle[lA], neB = c_nle[lB];

    __half2* tabA = tab;
    __half2* tabB = tab + (neA + 1);

    // stage both tables ONCE (persistent over ~58K points)
    const float2* __restrict__ srcA =
        reinterpret_cast<const float2*>(emb) + (size_t)lA * (NENC + 1);
    const float2* __restrict__ srcB =
        reinterpret_cast<const float2*>(emb) + (size_t)lB * (NENC + 1);
    for (int i = threadIdx.x; i <= neA; i += TPB) {
        const float2 v = srcA[i];
        tabA[i] = __floats2half2_rn(v.x * SCALE, v.y * SCALE);
    }
    for (int i = threadIdx.x; i <= neB; i += TPB) {
        const float2 v = srcB[i];
        tabB[i] = __floats2half2_rn(v.x * SCALE, v.y * SCALE);
    }
    __syncthreads();

    uint2* __restrict__ stage = g_stage + (size_t)m * NPTS;

    const int pend = min((slice + 1) * SLICE, NPTS);
    #pragma unroll 1
    for (int p = slice * SLICE + threadIdx.x; p < pend; p += TPB) {
        const float xv0 = g_xs[p];
        const float xv1 = g_xs[NPTS + p];
        const float xv2 = g_xs[2u * NPTS + p];

        __half2 rA, rB;
        if (lA < 3) rA = level_feat<true >(tabA, RA, xv0, xv1, xv2);
        else        rA = level_feat<false>(tabA, RA, xv0, xv1, xv2);
        if (lB < 3) rB = level_feat<true >(tabB, RB, xv0, xv1, xv2);
        else        rB = level_feat<false>(tabB, RB, xv0, xv1, xv2);

        stage[p] = make_uint2(*reinterpret_cast<unsigned*>(&rA),
                              *reinterpret_cast<unsigned*>(&rB));
    }
}

// ---------------------------------------------------------------- transpose
#define TPB3 512
__global__ __launch_bounds__(TPB3)
void transpose_out_kernel(float4* __restrict__ out)
{
    __shared__ uint2 arr[TPB3][NPAIR + 1];        // [point][pair], pitch 9

    const int base = blockIdx.x * TPB3;
    const int tid  = threadIdx.x;

    #pragma unroll
    for (int m = 0; m < NPAIR; ++m)
        arr[tid][m] = g_stage[(size_t)m * NPTS + base + tid];
    __syncthreads();

    #pragma unroll
    for (int k = 0; k < 8; ++k) {
        const int local = k * TPB3 + tid;         // float4 index within block
        const int p_off = local >> 3;
        const int m     = local & 7;
        const uint2 v = arr[p_off][m];
        const float2 fa = __half22float2(*reinterpret_cast<const __half2*>(&v.x));
        const float2 fb = __half22float2(*reinterpret_cast<const __half2*>(&v.y));
        // streaming store: don't let the 128MB output evict the L2-resident stage
        __stcs(&out[(size_t)base * 8 + local],
               make_float4(fa.x * INV_SCALE, fa.y * INV_SCALE,
                           fb.x * INV_SCALE, fb.y * INV_SCALE));
    }
}

// ---------------------------------------------------------------- launch
extern "C" void kernel_launch(void* const* d_in, const int* in_sizes, int n_in,
                              void* d_out, int out_size)
{
    (void)n_in; (void)out_size;
    const float* x;
    const float* emb;
    if (in_sizes[0] == 3 * NPTS) { x = (const float*)d_in[0]; emb = (const float*)d_in[1]; }
    else                         { x = (const float*)d_in[1]; emb = (const float*)d_in[0]; }
    float4* out = (float4*)d_out;

    cudaFuncSetAttribute(hashgrid_pair_kernel,
                         cudaFuncAttributeMaxDynamicSharedMemorySize, SMEM_BYTES);

    transpose_x_kernel<<<NPTS / 4 / 256, 256>>>(
        reinterpret_cast<const float4*>(x));

    const int blocks = NPAIR * NSLICE;            // 144 = exactly 1 wave
    hashgrid_pair_kernel<<<blocks, TPB, SMEM_BYTES>>>(emb);

    transpose_out_kernel<<<NPTS / TPB3, TPB3>>>(out);
}

// round 14
// speedup vs baseline: 1.0750x; 1.0525x over previous
#include <cuda_runtime.h>
#include <cuda_fp16.h>
#include <stdint.h>

// MultiLevelSparseHashEncoding — round 14.
// Fix a wave-sizing error: GB300 has 152 SMs (not 148).  Main grid
// NSLICE 18 -> 19: 152 blocks = exactly 1 CTA/SM (was idling 8 SMs).
// Out-transpose reverted to the measured-best R9 form (TPB 256, plain
// stores) + __ldcs on the read-once stage loads.  Everything else is the
// validated R9 configuration (101.5us, rel_err 5.23e-4).

#define NLVL 16
#define NENC 16384
#define NPTS (1 << 20)
#define TPB  1024
#define NPAIR 8
#define NSLICE 19
#define SLICE ((NPTS + NSLICE - 1) / NSLICE)       // 55189
#define SMEM_BYTES ((2 * (NENC + 1)) * (int)sizeof(__half2))   // 131080
#define SCALE    4096.0f
#define INV_SCALE (1.0f / 4096.0f)

__constant__ int c_res[NLVL] = {16, 20, 25, 32, 40, 50, 64, 80,
                                101, 128, 161, 203, 256, 322, 406, 512};
__constant__ int c_nle[NLVL] = {4096, 8000, 15625, 16384, 16384, 16384,
                                16384, 16384, 16384, 16384, 16384, 16384,
                                16384, 16384, 16384, 16384};

__device__ float g_xs[3u * NPTS];                  // SoA coords (12 MB)
__device__ uint2 g_stage[(size_t)NPAIR * NPTS];    // [pair][point] half4 bits

// ---------------------------------------------------------------- pre-kernel
// 4 points per thread: 3 float4 loads -> 3 float4 plane stores
__global__ __launch_bounds__(256)
void transpose_x_kernel(const float4* __restrict__ x4)
{
    const int i = blockIdx.x * 256 + threadIdx.x;      // float4-group index
    const float4 a = x4[3 * i + 0];                    // x0 y0 z0 x1
    const float4 b = x4[3 * i + 1];                    // y1 z1 x2 y2
    const float4 c = x4[3 * i + 2];                    // z2 x3 y3 z3
    float4* __restrict__ p0 = reinterpret_cast<float4*>(g_xs);
    float4* __restrict__ p1 = reinterpret_cast<float4*>(g_xs + NPTS);
    float4* __restrict__ p2 = reinterpret_cast<float4*>(g_xs + 2u * NPTS);
    p0[i] = make_float4(a.x, a.w, b.z, c.y);
    p1[i] = make_float4(a.y, b.x, b.w, c.z);
    p2[i] = make_float4(a.z, b.y, c.x, c.w);
}

// ---------------------------------------------------------------- per-level
// returns the fp16 accumulator still scaled by 2^12
template <bool DIRECT>
__device__ __forceinline__ __half2
level_feat(const __half2* __restrict__ tab, const int R,
           const float xv0, const float xv1, const float xv2)
{
    const float halfR = 0.5f * (float)R;
    const float cadd  = halfR - 0.5f;
    const float t0 = fmaf(xv0, halfR, cadd);
    const float t1 = fmaf(xv1, halfR, cadd);
    const float t2 = fmaf(xv2, halfR, cadd);

    const float fl0 = floorf(t0), fl1 = floorf(t1), fl2 = floorf(t2);
    const float fr0 = t0 - fl0, fr1 = t1 - fl1, fr2 = t2 - fl2;
    const int   i0  = (int)fl0, i1 = (int)fl1, i2 = (int)fl2;

    // validity folded into per-dim weights: invalid corner -> weight 0
    const float wx0 = i0     >= 0 ? 1.0f - fr0 : 0.0f;
    const float wx1 = i0 + 1 <  R ? fr0        : 0.0f;
    const float wy0 = i1     >= 0 ? 1.0f - fr1 : 0.0f;
    const float wy1 = i1 + 1 <  R ? fr1        : 0.0f;
    const float wz[2] = {i2     >= 0 ? 1.0f - fr2 : 0.0f,
                         i2 + 1 <  R ? fr2        : 0.0f};
    const float wxy[4] = {wx0 * wy0, wx0 * wy1, wx1 * wy0, wx1 * wy1};

    unsigned kx[2], kyz[4];
    if (DIRECT) {
        const int R2 = R * R;
        const int a0 = max(i0, 0), a1 = min(i0 + 1, R - 1);
        const int b0 = max(i1, 0), b1 = min(i1 + 1, R - 1);
        const int d0 = max(i2, 0), d1 = min(i2 + 1, R - 1);
        kx[0] = (unsigned)(a0 * R2); kx[1] = (unsigned)(a1 * R2);
        kyz[0] = (unsigned)(b0 * R + d0); kyz[1] = (unsigned)(b0 * R + d1);
        kyz[2] = (unsigned)(b1 * R + d0); kyz[3] = (unsigned)(b1 * R + d1);
    } else {
        kx[0] = (unsigned)i0; kx[1] = (unsigned)(i0 + 1);
        const unsigned hy0 = (unsigned)i1 * 2654435761u;
        const unsigned hy1 = hy0 + 2654435761u;
        const unsigned hz0 = (unsigned)i2 * 805459861u;
        const unsigned hz1 = hz0 + 805459861u;
        kyz[0] = hy0 ^ hz0; kyz[1] = hy0 ^ hz1;
        kyz[2] = hy1 ^ hz0; kyz[3] = hy1 ^ hz1;
    }
    const unsigned mask = NENC - 1;

    __half2 acc = __float2half2_rn(0.0f);
    #pragma unroll
    for (int c = 0; c < 8; ++c) {
        const int ox = (c >> 2) & 1, oyz = c & 3;
        unsigned id;
        if (DIRECT) id = kx[ox] + kyz[oyz];
        else        id = (kx[ox] ^ kyz[oyz]) & mask;   // single LOP3
        const float   w  = wxy[2 * ox + (oyz >> 1)] * wz[oyz & 1];
        const __half2 w2 = __float2half2_rn(w);
        acc = __hfma2(w2, tab[id], acc);
    }
    return acc;
}

// ---------------------------------------------------------------- main
__global__ __launch_bounds__(TPB, 1)
void hashgrid_pair_kernel(const float* __restrict__ emb)
{
    extern __shared__ __half2 tab[];

    const int m     = blockIdx.x & (NPAIR - 1);   // pair index (fastest)
    const int slice = blockIdx.x >> 3;            // 0..NSLICE-1
    const int lA = 2 * m, lB = 2 * m + 1;
    const int RA = c_res[lA], RB = c_res[lB];
    const int neA = c_nle[lA], neB = c_nle[lB];

    __half2* tabA = tab;
    __half2* tabB = tab + (neA + 1);

    // stage both tables ONCE (persistent over ~55K points)
    const float2* __restrict__ srcA =
        reinterpret_cast<const float2*>(emb) + (size_t)lA * (NENC + 1);
    const float2* __restrict__ srcB =
        reinterpret_cast<const float2*>(emb) + (size_t)lB * (NENC + 1);
    for (int i = threadIdx.x; i <= neA; i += TPB) {
        const float2 v = srcA[i];
        tabA[i] = __floats2half2_rn(v.x * SCALE, v.y * SCALE);
    }
    for (int i = threadIdx.x; i <= neB; i += TPB) {
        const float2 v = srcB[i];
        tabB[i] = __floats2half2_rn(v.x * SCALE, v.y * SCALE);
    }
    __syncthreads();

    uint2* __restrict__ stage = g_stage + (size_t)m * NPTS;

    const int pend = min((slice + 1) * SLICE, NPTS);
    #pragma unroll 1
    for (int p = slice * SLICE + threadIdx.x; p < pend; p += TPB) {
        const float xv0 = g_xs[p];
        const float xv1 = g_xs[NPTS + p];
        const float xv2 = g_xs[2u * NPTS + p];

        __half2 rA, rB;
        if (lA < 3) rA = level_feat<true >(tabA, RA, xv0, xv1, xv2);
        else        rA = level_feat<false>(tabA, RA, xv0, xv1, xv2);
        if (lB < 3) rB = level_feat<true >(tabB, RB, xv0, xv1, xv2);
        else        rB = level_feat<false>(tabB, RB, xv0, xv1, xv2);

        stage[p] = make_uint2(*reinterpret_cast<unsigned*>(&rA),
                              *reinterpret_cast<unsigned*>(&rB));
    }
}

// ---------------------------------------------------------------- transpose
#define TPB3 256
__global__ __launch_bounds__(TPB3)
void transpose_out_kernel(float4* __restrict__ out)
{
    __shared__ uint2 arr[TPB3][NPAIR + 1];        // [point][pair], pitch 9

    const int base = blockIdx.x * TPB3;
    const int tid  = threadIdx.x;

    #pragma unroll
    for (int m = 0; m < NPAIR; ++m)
        arr[tid][m] = __ldcs(&g_stage[(size_t)m * NPTS + base + tid]);
    __syncthreads();

    #pragma unroll
    for (int k = 0; k < 8; ++k) {
        const int local = k * TPB3 + tid;         // float4 index within block
        const int p_off = local >> 3;
        const int m     = local & 7;
        const uint2 v = arr[p_off][m];
        const float2 fa = __half22float2(*reinterpret_cast<const __half2*>(&v.x));
        const float2 fb = __half22float2(*reinterpret_cast<const __half2*>(&v.y));
        out[(size_t)base * 8 + local] =
            make_float4(fa.x * INV_SCALE, fa.y * INV_SCALE,
                        fb.x * INV_SCALE, fb.y * INV_SCALE);
    }
}

// ---------------------------------------------------------------- launch
extern "C" void kernel_launch(void* const* d_in, const int* in_sizes, int n_in,
                              void* d_out, int out_size)
{
    (void)n_in; (void)out_size;
    const float* x;
    const float* emb;
    if (in_sizes[0] == 3 * NPTS) { x = (const float*)d_in[0]; emb = (const float*)d_in[1]; }
    else                         { x = (const float*)d_in[1]; emb = (const float*)d_in[0]; }
    float4* out = (float4*)d_out;

    cudaFuncSetAttribute(hashgrid_pair_kernel,
                         cudaFuncAttributeMaxDynamicSharedMemorySize, SMEM_BYTES);

    transpose_x_kernel<<<NPTS / 4 / 256, 256>>>(
        reinterpret_cast<const float4*>(x));

    const int blocks = NPAIR * NSLICE;            // 152 = 1 CTA per GB300 SM
    hashgrid_pair_kernel<<<blocks, TPB, SMEM_BYTES>>>(emb);

    transpose_out_kernel<<<NPTS / TPB3, TPB3>>>(out);
}

// round 15
// speedup vs baseline: 1.0883x; 1.0124x over previous
#include <cuda_runtime.h>
#include <cuda_fp16.h>
#include <stdint.h>

// MultiLevelSparseHashEncoding — round 15.
// vs R14 (96.8us = xT 6.7 + main ~70 + outT ~20): DELETE the x-transpose
// kernel.  Main now reads AoS x directly, 4 consecutive points per thread
// via 3x LDG.128 + register shuffle (identical L1 wavefront cost to the
// SoA path), and writes the 4 results as 2x STG.128.  Saves the 6.7us
// pre-kernel + 24MB of DRAM round-trip.  Math byte-identical to R14.

#define NLVL 16
#define NENC 16384
#define NPTS (1 << 20)
#define TPB  1024
#define NPAIR 8
#define NSLICE 19
#define SLICE 55192                                // mult of 4; 19*55192 >= 2^20
#define SMEM_BYTES ((2 * (NENC + 1)) * (int)sizeof(__half2))   // 131080
#define SCALE    4096.0f
#define INV_SCALE (1.0f / 4096.0f)

__constant__ int c_res[NLVL] = {16, 20, 25, 32, 40, 50, 64, 80,
                                101, 128, 161, 203, 256, 322, 406, 512};
__constant__ int c_nle[NLVL] = {4096, 8000, 15625, 16384, 16384, 16384,
                                16384, 16384, 16384, 16384, 16384, 16384,
                                16384, 16384, 16384, 16384};

__device__ uint2 g_stage[(size_t)NPAIR * NPTS];    // [pair][point] half4 bits

// ---------------------------------------------------------------- per-level
// returns the fp16 accumulator still scaled by 2^12
template <bool DIRECT>
__device__ __forceinline__ __half2
level_feat(const __half2* __restrict__ tab, const int R,
           const float xv0, const float xv1, const float xv2)
{
    const float halfR = 0.5f * (float)R;
    const float cadd  = halfR - 0.5f;
    const float t0 = fmaf(xv0, halfR, cadd);
    const float t1 = fmaf(xv1, halfR, cadd);
    const float t2 = fmaf(xv2, halfR, cadd);

    const float fl0 = floorf(t0), fl1 = floorf(t1), fl2 = floorf(t2);
    const float fr0 = t0 - fl0, fr1 = t1 - fl1, fr2 = t2 - fl2;
    const int   i0  = (int)fl0, i1 = (int)fl1, i2 = (int)fl2;

    // validity folded into per-dim weights: invalid corner -> weight 0
    const float wx0 = i0     >= 0 ? 1.0f - fr0 : 0.0f;
    const float wx1 = i0 + 1 <  R ? fr0        : 0.0f;
    const float wy0 = i1     >= 0 ? 1.0f - fr1 : 0.0f;
    const float wy1 = i1 + 1 <  R ? fr1        : 0.0f;
    const float wz[2] = {i2     >= 0 ? 1.0f - fr2 : 0.0f,
                         i2 + 1 <  R ? fr2        : 0.0f};
    const float wxy[4] = {wx0 * wy0, wx0 * wy1, wx1 * wy0, wx1 * wy1};

    unsigned kx[2], kyz[4];
    if (DIRECT) {
        const int R2 = R * R;
        const int a0 = max(i0, 0), a1 = min(i0 + 1, R - 1);
        const int b0 = max(i1, 0), b1 = min(i1 + 1, R - 1);
        const int d0 = max(i2, 0), d1 = min(i2 + 1, R - 1);
        kx[0] = (unsigned)(a0 * R2); kx[1] = (unsigned)(a1 * R2);
        kyz[0] = (unsigned)(b0 * R + d0); kyz[1] = (unsigned)(b0 * R + d1);
        kyz[2] = (unsigned)(b1 * R + d0); kyz[3] = (unsigned)(b1 * R + d1);
    } else {
        kx[0] = (unsigned)i0; kx[1] = (unsigned)(i0 + 1);
        const unsigned hy0 = (unsigned)i1 * 2654435761u;
        const unsigned hy1 = hy0 + 2654435761u;
        const unsigned hz0 = (unsigned)i2 * 805459861u;
        const unsigned hz1 = hz0 + 805459861u;
        kyz[0] = hy0 ^ hz0; kyz[1] = hy0 ^ hz1;
        kyz[2] = hy1 ^ hz0; kyz[3] = hy1 ^ hz1;
    }
    const unsigned mask = NENC - 1;

    __half2 acc = __float2half2_rn(0.0f);
    #pragma unroll
    for (int c = 0; c < 8; ++c) {
        const int ox = (c >> 2) & 1, oyz = c & 3;
        unsigned id;
        if (DIRECT) id = kx[ox] + kyz[oyz];
        else        id = (kx[ox] ^ kyz[oyz]) & mask;   // single LOP3
        const float   w  = wxy[2 * ox + (oyz >> 1)] * wz[oyz & 1];
        const __half2 w2 = __float2half2_rn(w);
        acc = __hfma2(w2, tab[id], acc);
    }
    return acc;
}

// ---------------------------------------------------------------- main
__global__ __launch_bounds__(TPB, 1)
void hashgrid_pair_kernel(const float* __restrict__ emb,
                          const float4* __restrict__ x4)
{
    extern __shared__ __half2 tab[];

    const int m     = blockIdx.x & (NPAIR - 1);   // pair index (fastest)
    const int slice = blockIdx.x >> 3;            // 0..NSLICE-1
    const int lA = 2 * m, lB = 2 * m + 1;
    const int RA = c_res[lA], RB = c_res[lB];
    const int neA = c_nle[lA], neB = c_nle[lB];

    __half2* tabA = tab;
    __half2* tabB = tab + (neA + 1);

    // stage both tables ONCE (persistent over ~55K points)
    const float2* __restrict__ srcA =
        reinterpret_cast<const float2*>(emb) + (size_t)lA * (NENC + 1);
    const float2* __restrict__ srcB =
        reinterpret_cast<const float2*>(emb) + (size_t)lB * (NENC + 1);
    for (int i = threadIdx.x; i <= neA; i += TPB) {
        const float2 v = srcA[i];
        tabA[i] = __floats2half2_rn(v.x * SCALE, v.y * SCALE);
    }
    for (int i = threadIdx.x; i <= neB; i += TPB) {
        const float2 v = srcB[i];
        tabB[i] = __floats2half2_rn(v.x * SCALE, v.y * SCALE);
    }
    __syncthreads();

    uint4* __restrict__ stage4 =
        reinterpret_cast<uint4*>(g_stage + (size_t)m * NPTS);

    // 4 consecutive points per thread: 3x LDG.128 + shuffle, 2x STG.128
    const int base4 = (slice * SLICE) / 4;
    const int end4  = min((slice + 1) * SLICE, NPTS) / 4;
    #pragma unroll 1
    for (int i = base4 + threadIdx.x; i < end4; i += TPB) {
        const float4 a = x4[3 * i + 0];            // x0 y0 z0 x1
        const float4 b = x4[3 * i + 1];            // y1 z1 x2 y2
        const float4 c = x4[3 * i + 2];            // z2 x3 y3 z3
        const float px[4] = {a.x, a.w, b.z, c.y};
        const float py[4] = {a.y, b.x, b.w, c.z};
        const float pz[4] = {a.z, b.y, c.x, c.w};

        unsigned r[8];
        #pragma unroll
        for (int k = 0; k < 4; ++k) {
            __half2 rA, rB;
            if (lA < 3) rA = level_feat<true >(tabA, RA, px[k], py[k], pz[k]);
            else        rA = level_feat<false>(tabA, RA, px[k], py[k], pz[k]);
            if (lB < 3) rB = level_feat<true >(tabB, RB, px[k], py[k], pz[k]);
            else        rB = level_feat<false>(tabB, RB, px[k], py[k], pz[k]);
            r[2 * k]     = *reinterpret_cast<unsigned*>(&rA);
            r[2 * k + 1] = *reinterpret_cast<unsigned*>(&rB);
        }
        stage4[2 * i]     = make_uint4(r[0], r[1], r[2], r[3]);
        stage4[2 * i + 1] = make_uint4(r[4], r[5], r[6], r[7]);
    }
}

// ---------------------------------------------------------------- transpose
#define TPB3 256
__global__ __launch_bounds__(TPB3)
void transpose_out_kernel(float4* __restrict__ out)
{
    __shared__ uint2 arr[TPB3][NPAIR + 1];        // [point][pair], pitch 9

    const int base = blockIdx.x * TPB3;
    const int tid  = threadIdx.x;

    #pragma unroll
    for (int m = 0; m < NPAIR; ++m)
        arr[tid][m] = __ldcs(&g_stage[(size_t)m * NPTS + base + tid]);
    __syncthreads();

    #pragma unroll
    for (int k = 0; k < 8; ++k) {
        const int local = k * TPB3 + tid;         // float4 index within block
        const int p_off = local >> 3;
        const int m     = local & 7;
        const uint2 v = arr[p_off][m];
        const float2 fa = __half22float2(*reinterpret_cast<const __half2*>(&v.x));
        const float2 fb = __half22float2(*reinterpret_cast<const __half2*>(&v.y));
        out[(size_t)base * 8 + local] =
            make_float4(fa.x * INV_SCALE, fa.y * INV_SCALE,
                        fb.x * INV_SCALE, fb.y * INV_SCALE);
    }
}

// ---------------------------------------------------------------- launch
extern "C" void kernel_launch(void* const* d_in, const int* in_sizes, int n_in,
                              void* d_out, int out_size)
{
    (void)n_in; (void)out_size;
    const float* x;
    const float* emb;
    if (in_sizes[0] == 3 * NPTS) { x = (const float*)d_in[0]; emb = (const float*)d_in[1]; }
    else                         { x = (const float*)d_in[1]; emb = (const float*)d_in[0]; }
    float4* out = (float4*)d_out;

    cudaFuncSetAttribute(hashgrid_pair_kernel,
                         cudaFuncAttributeMaxDynamicSharedMemorySize, SMEM_BYTES);

    const int blocks = NPAIR * NSLICE;            // 152 = 1 CTA per GB300 SM
    hashgrid_pair_kernel<<<blocks, TPB, SMEM_BYTES>>>(
        emb, reinterpret_cast<const float4*>(x));

    transpose_out_kernel<<<NPTS / TPB3, TPB3>>>(out);
}

// round 16
// speedup vs baseline: 1.0990x; 1.0098x over previous
#include <cuda_runtime.h>
#include <cuda_fp16.h>
#include <stdint.h>

// MultiLevelSparseHashEncoding — round 16.
// R15: main is at its gather floor (~65us); out-transpose measured 30.8us
// at only 58% DRAM (latency-limited, 8x LDG.64/thread too little MLP).
// This round widens out-T only:
//  * 512 points/block; uint4 loads (2 pts per plane per thread) -> 8x
//    LDG.128/thread, 2x bytes in flight, half the per-byte issue cost.
//  * SMEM arr[plane][514] uint2: STS.128 store phase conflict-free; read
//    phase <=2-way on 8B accesses (at the 2-wavefront floor).
// Main kernel byte-identical to R15 (95.6us, rel_err 5.23e-4).

#define NLVL 16
#define NENC 16384
#define NPTS (1 << 20)
#define TPB  1024
#define NPAIR 8
#define NSLICE 19
#define SLICE 55192                                // mult of 4; 19*55192 >= 2^20
#define SMEM_BYTES ((2 * (NENC + 1)) * (int)sizeof(__half2))   // 131080
#define SCALE    4096.0f
#define INV_SCALE (1.0f / 4096.0f)

__constant__ int c_res[NLVL] = {16, 20, 25, 32, 40, 50, 64, 80,
                                101, 128, 161, 203, 256, 322, 406, 512};
__constant__ int c_nle[NLVL] = {4096, 8000, 15625, 16384, 16384, 16384,
                                16384, 16384, 16384, 16384, 16384, 16384,
                                16384, 16384, 16384, 16384};

__device__ uint2 g_stage[(size_t)NPAIR * NPTS];    // [pair][point] half4 bits

// ---------------------------------------------------------------- per-level
// returns the fp16 accumulator still scaled by 2^12
template <bool DIRECT>
__device__ __forceinline__ __half2
level_feat(const __half2* __restrict__ tab, const int R,
           const float xv0, const float xv1, const float xv2)
{
    const float halfR = 0.5f * (float)R;
    const float cadd  = halfR - 0.5f;
    const float t0 = fmaf(xv0, halfR, cadd);
    const float t1 = fmaf(xv1, halfR, cadd);
    const float t2 = fmaf(xv2, halfR, cadd);

    const float fl0 = floorf(t0), fl1 = floorf(t1), fl2 = floorf(t2);
    const float fr0 = t0 - fl0, fr1 = t1 - fl1, fr2 = t2 - fl2;
    const int   i0  = (int)fl0, i1 = (int)fl1, i2 = (int)fl2;

    // validity folded into per-dim weights: invalid corner -> weight 0
    const float wx0 = i0     >= 0 ? 1.0f - fr0 : 0.0f;
    const float wx1 = i0 + 1 <  R ? fr0        : 0.0f;
    const float wy0 = i1     >= 0 ? 1.0f - fr1 : 0.0f;
    const float wy1 = i1 + 1 <  R ? fr1        : 0.0f;
    const float wz[2] = {i2     >= 0 ? 1.0f - fr2 : 0.0f,
                         i2 + 1 <  R ? fr2        : 0.0f};
    const float wxy[4] = {wx0 * wy0, wx0 * wy1, wx1 * wy0, wx1 * wy1};

    unsigned kx[2], kyz[4];
    if (DIRECT) {
        const int R2 = R * R;
        const int a0 = max(i0, 0), a1 = min(i0 + 1, R - 1);
        const int b0 = max(i1, 0), b1 = min(i1 + 1, R - 1);
        const int d0 = max(i2, 0), d1 = min(i2 + 1, R - 1);
        kx[0] = (unsigned)(a0 * R2); kx[1] = (unsigned)(a1 * R2);
        kyz[0] = (unsigned)(b0 * R + d0); kyz[1] = (unsigned)(b0 * R + d1);
        kyz[2] = (unsigned)(b1 * R + d0); kyz[3] = (unsigned)(b1 * R + d1);
    } else {
        kx[0] = (unsigned)i0; kx[1] = (unsigned)(i0 + 1);
        const unsigned hy0 = (unsigned)i1 * 2654435761u;
        const unsigned hy1 = hy0 + 2654435761u;
        const unsigned hz0 = (unsigned)i2 * 805459861u;
        const unsigned hz1 = hz0 + 805459861u;
        kyz[0] = hy0 ^ hz0; kyz[1] = hy0 ^ hz1;
        kyz[2] = hy1 ^ hz0; kyz[3] = hy1 ^ hz1;
    }
    const unsigned mask = NENC - 1;

    __half2 acc = __float2half2_rn(0.0f);
    #pragma unroll
    for (int c = 0; c < 8; ++c) {
        const int ox = (c >> 2) & 1, oyz = c & 3;
        unsigned id;
        if (DIRECT) id = kx[ox] + kyz[oyz];
        else        id = (kx[ox] ^ kyz[oyz]) & mask;   // single LOP3
        const float   w  = wxy[2 * ox + (oyz >> 1)] * wz[oyz & 1];
        const __half2 w2 = __float2half2_rn(w);
        acc = __hfma2(w2, tab[id], acc);
    }
    return acc;
}

// ---------------------------------------------------------------- main
__global__ __launch_bounds__(TPB, 1)
void hashgrid_pair_kernel(const float* __restrict__ emb,
                          const float4* __restrict__ x4)
{
    extern __shared__ __half2 tab[];

    const int m     = blockIdx.x & (NPAIR - 1);   // pair index (fastest)
    const int slice = blockIdx.x >> 3;            // 0..NSLICE-1
    const int lA = 2 * m, lB = 2 * m + 1;
    const int RA = c_res[lA], RB = c_res[lB];
    const int neA = c_nle[lA], neB = c_nle[lB];

    __half2* tabA = tab;
    __half2* tabB = tab + (neA + 1);

    // stage both tables ONCE (persistent over ~55K points)
    const float2* __restrict__ srcA =
        reinterpret_cast<const float2*>(emb) + (size_t)lA * (NENC + 1);
    const float2* __restrict__ srcB =
        reinterpret_cast<const float2*>(emb) + (size_t)lB * (NENC + 1);
    for (int i = threadIdx.x; i <= neA; i += TPB) {
        const float2 v = srcA[i];
        tabA[i] = __floats2half2_rn(v.x * SCALE, v.y * SCALE);
    }
    for (int i = threadIdx.x; i <= neB; i += TPB) {
        const float2 v = srcB[i];
        tabB[i] = __floats2half2_rn(v.x * SCALE, v.y * SCALE);
    }
    __syncthreads();

    uint4* __restrict__ stage4 =
        reinterpret_cast<uint4*>(g_stage + (size_t)m * NPTS);

    // 4 consecutive points per thread: 3x LDG.128 + shuffle, 2x STG.128
    const int base4 = (slice * SLICE) / 4;
    const int end4  = min((slice + 1) * SLICE, NPTS) / 4;
    #pragma unroll 1
    for (int i = base4 + threadIdx.x; i < end4; i += TPB) {
        const float4 a = x4[3 * i + 0];            // x0 y0 z0 x1
        const float4 b = x4[3 * i + 1];            // y1 z1 x2 y2
        const float4 c = x4[3 * i + 2];            // z2 x3 y3 z3
        const float px[4] = {a.x, a.w, b.z, c.y};
        const float py[4] = {a.y, b.x, b.w, c.z};
        const float pz[4] = {a.z, b.y, c.x, c.w};

        unsigned r[8];
        #pragma unroll
        for (int k = 0; k < 4; ++k) {
            __half2 rA, rB;
            if (lA < 3) rA = level_feat<true >(tabA, RA, px[k], py[k], pz[k]);
            else        rA = level_feat<false>(tabA, RA, px[k], py[k], pz[k]);
            if (lB < 3) rB = level_feat<true >(tabB, RB, px[k], py[k], pz[k]);
            else        rB = level_feat<false>(tabB, RB, px[k], py[k], pz[k]);
            r[2 * k]     = *reinterpret_cast<unsigned*>(&rA);
            r[2 * k + 1] = *reinterpret_cast<unsigned*>(&rB);
        }
        stage4[2 * i]     = make_uint4(r[0], r[1], r[2], r[3]);
        stage4[2 * i + 1] = make_uint4(r[4], r[5], r[6], r[7]);
    }
}

// ---------------------------------------------------------------- transpose
// 512 points per 256-thread block; uint4 plane loads (2 pts/thread/plane)
#define TPB3 256
#define PPT  512                                   // points per block
__global__ __launch_bounds__(TPB3)
void transpose_out_kernel(float4* __restrict__ out)
{
    __shared__ uint2 arr[NPAIR][PPT + 2];          // [plane][point], pad 2

    const int base = blockIdx.x * PPT;
    const int tid  = threadIdx.x;

    // load phase: thread t loads points 2t, 2t+1 of each plane (LDG.128)
    const uint4* __restrict__ st4 = reinterpret_cast<const uint4*>(g_stage);
    #pragma unroll
    for (int m = 0; m < NPAIR; ++m) {
        const uint4 v = __ldcs(&st4[((size_t)m * NPTS + base) / 2 + tid]);
        *reinterpret_cast<uint4*>(&arr[m][2 * tid]) = v;   // STS.128
    }
    __syncthreads();

    // write phase: 4096 float4 per block, 16 per thread, fully coalesced
    #pragma unroll
    for (int k = 0; k < 16; ++k) {
        const int local = k * TPB3 + tid;          // float4 index within block
        const int p_off = local >> 3;
        const int m     = local & 7;
        const uint2 v = arr[m][p_off];
        const float2 fa = __half22float2(*reinterpret_cast<const __half2*>(&v.x));
        const float2 fb = __half22float2(*reinterpret_cast<const __half2*>(&v.y));
        out[(size_t)base * 8 + local] =
            make_float4(fa.x * INV_SCALE, fa.y * INV_SCALE,
                        fb.x * INV_SCALE, fb.y * INV_SCALE);
    }
}

// ---------------------------------------------------------------- launch
extern "C" void kernel_launch(void* const* d_in, const int* in_sizes, int n_in,
                              void* d_out, int out_size)
{
    (void)n_in; (void)out_size;
    const float* x;
    const float* emb;
    if (in_sizes[0] == 3 * NPTS) { x = (const float*)d_in[0]; emb = (const float*)d_in[1]; }
    else                         { x = (const float*)d_in[1]; emb = (const float*)d_in[0]; }
    float4* out = (float4*)d_out;

    cudaFuncSetAttribute(hashgrid_pair_kernel,
                         cudaFuncAttributeMaxDynamicSharedMemorySize, SMEM_BYTES);

    const int blocks = NPAIR * NSLICE;            // 152 = 1 CTA per GB300 SM
    hashgrid_pair_kernel<<<blocks, TPB, SMEM_BYTES>>>(
        emb, reinterpret_cast<const float4*>(x));

    transpose_out_kernel<<<NPTS / PPT, TPB3>>>(out);
}